// round 8
// baseline (speedup 1.0000x reference)
#include <cuda_runtime.h>
#include <cstdint>

#define IMG_W 512
#define IMG_H 512
#define PLANES 64
#define PLANE_STRIDE (IMG_H * IMG_W)
#define NPIX (PLANES * PLANE_STRIDE)

#define STRIP 32                 // rows per warp-unit
#define STRIPS 16                // 512/32
#define SPANW 128                // cols per warp-unit
#define NSPAN 4                  // 512/128
#define NBLOCKS 512              // 4096 warp units / 8 warps per CTA
#define EPS 1e-10f

#define SLOTS 6                  // ring slots per warp (row pairs window)
#define CHUNKS 34                // 16B chunks per img-row: 1 halo + 32 + 1 halo
#define ROWF (CHUNKS * 4)        // 136 floats per img-row
#define IMG_STRIDE_B (ROWF * 4)          // 544 B
#define SLOT_STRIDE_B (2 * IMG_STRIDE_B) // 1088 B
#define WARP_RING_B (SLOTS * SLOT_STRIDE_B) // 6528 B
#define SMEM_BYTES (8 * WARP_RING_B)     // 52224 B per CTA

// persistent scratch (statically zero-init; last block resets each call)
__device__ double g_acc;
__device__ unsigned int g_count;

__device__ __forceinline__ void cp16(uint32_t dst, const float* src) {
    asm volatile("cp.async.cg.shared.global [%0], [%1], 16;" :: "r"(dst), "l"(src) : "memory");
}
__device__ __forceinline__ void cp_commit() {
    asm volatile("cp.async.commit_group;" ::: "memory");
}
__device__ __forceinline__ void cp_wait1() {
    asm volatile("cp.async.wait_group 1;" ::: "memory");
}
__device__ __forceinline__ void cp_wait0() {
    asm volatile("cp.async.wait_group 0;" ::: "memory");
}

__global__ void __launch_bounds__(256, 4) ngf_kernel(
    const float* __restrict__ I0, const float* __restrict__ I1,
    float* __restrict__ out)
{
    extern __shared__ float ring[];          // [8 warps][6 slots][2 img][136 f]
    __shared__ float warp_part[8];

    const int t    = threadIdx.x;
    const int lane = t & 31;
    const int wid  = t >> 5;

    // warp-unit decode: w = plane*64 + strip*4 + span
    const int w     = blockIdx.x * 8 + wid;
    const int plane = w >> 6;
    const int strip = (w >> 2) & (STRIPS - 1);
    const int span  = w & (NSPAN - 1);
    const int R0    = strip * STRIP;
    const int C0    = span * SPANW;

    const float* __restrict__ b0 = I0 + plane * PLANE_STRIDE;
    const float* __restrict__ b1 = I1 + plane * PLANE_STRIDE;

    float* wring = ring + wid * (WARP_RING_B / 4);
    const uint32_t sring = (uint32_t)__cvta_generic_to_shared(wring);

    // this lane's chunk source columns (clamped at image edges), hoisted
    const int gcA = max(0, min(C0 - 4 + 4 * lane,        IMG_W - 4));  // chunk = lane
    const int gcB = max(0, min(C0 - 4 + 4 * (lane + 32), IMG_W - 4));  // chunk = lane+32 (lane<2)
    const uint32_t dA = (uint32_t)(16 * lane);
    const uint32_t dB = (uint32_t)(16 * (lane + 32));

    // group j loads rows k = 2j, 2j+1 (global row clamp(R0-1+k)) for BOTH images
    #define ISSUE_GROUP(j)                                                         \
        do {                                                                       \
            _Pragma("unroll")                                                      \
            for (int q = 0; q < 2; q++) {                                          \
                const int k  = 2 * (j) + q;                                        \
                const int g  = max(0, min(R0 - 1 + k, IMG_H - 1));                 \
                const uint32_t sb = sring + (uint32_t)((k % SLOTS) * SLOT_STRIDE_B);\
                const float* r0 = b0 + g * IMG_W;                                  \
                const float* r1 = b1 + g * IMG_W;                                  \
                cp16(sb + dA,                 r0 + gcA);                           \
                cp16(sb + IMG_STRIDE_B + dA,  r1 + gcA);                           \
                if (lane < 2) {                                                    \
                    cp16(sb + dB,                 r0 + gcB);                       \
                    cp16(sb + IMG_STRIDE_B + dB,  r1 + gcB);                       \
                }                                                                  \
            }                                                                      \
            cp_commit();                                                           \
        } while (0)

    ISSUE_GROUP(0);
    ISSUE_GROUP(1);

    // local float index of this lane's 4 cols: 4 + 4*lane; edge-lane halo indices
    const int lc = 4 + 4 * lane;
    const int il = (C0 == 0) ? 4 : 3;                  // lane 0 left halo (clamped)
    const int ir = (C0 + SPANW == IMG_W) ? 131 : 132;  // lane 31 right halo (clamped)

    float4 up0, up1, ce0, ce1;
    float s = 0.f;

    // one accumulation step for center row at ring slot 'cer' (k given via cer)
    #define ACCUM(cer, dn0v, dn1v)                                                 \
        do {                                                                       \
            const float4 dn0 = dn0v, dn1 = dn1v;                                   \
            float hl0 = __shfl_up_sync(0xFFFFFFFFu, ce0.w, 1);                     \
            float hr0 = __shfl_down_sync(0xFFFFFFFFu, ce0.x, 1);                   \
            float hl1 = __shfl_up_sync(0xFFFFFFFFu, ce1.w, 1);                     \
            float hr1 = __shfl_down_sync(0xFFFFFFFFu, ce1.x, 1);                   \
            if (lane == 0)  { hl0 = (cer)[il];        hl1 = (cer)[ROWF + il]; }    \
            if (lane == 31) { hr0 = (cer)[ir];        hr1 = (cer)[ROWF + ir]; }    \
            const float g0x[4] = { dn0.x-up0.x, dn0.y-up0.y, dn0.z-up0.z, dn0.w-up0.w };\
            const float g1x[4] = { dn1.x-up1.x, dn1.y-up1.y, dn1.z-up1.z, dn1.w-up1.w };\
            const float g0y[4] = { ce0.y-hl0, ce0.z-ce0.x, ce0.w-ce0.y, hr0-ce0.z };\
            const float g1y[4] = { ce1.y-hl1, ce1.z-ce1.x, ce1.w-ce1.y, hr1-ce1.z };\
            _Pragma("unroll")                                                      \
            for (int qq = 0; qq < 4; qq++) {                                       \
                const float n0  = fmaf(g0x[qq], g0x[qq], fmaf(g0y[qq], g0y[qq], EPS));\
                const float n1  = fmaf(g1x[qq], g1x[qq], fmaf(g1y[qq], g1y[qq], EPS));\
                const float dot = fmaf(g0x[qq], g1x[qq], g0y[qq] * g1y[qq]);       \
                s += __fdividef(dot * dot, n0 * n1);                               \
            }                                                                      \
            up0 = ce0; up1 = ce1; ce0 = dn0; ce1 = dn1;                            \
        } while (0)

    #define ROWP(k) (wring + ((k) % SLOTS) * (SLOT_STRIDE_B / 4))

#pragma unroll
    for (int i = 0; i < 16; i++) {
        if (i < 15) ISSUE_GROUP(i + 2);     // groups 2..16
        else        cp_commit();            // dummy keeps group count uniform
        cp_wait1();                         // groups <= i+1 done -> rows k <= 2i+3
        __syncwarp();                       // warp-scope visibility of all lanes' copies

        if (i == 0) {                       // init: up = row k=0, ce = row k=1
            const float* r0 = ROWP(0);
            const float* r1 = ROWP(1);
            up0 = ((const float4*)r0)[0 + lane];          up0 = *(const float4*)(r0 + lc);
            up1 = *(const float4*)(r0 + ROWF + lc);
            ce0 = *(const float4*)(r1 + lc);
            ce1 = *(const float4*)(r1 + ROWF + lc);
        }

        // row kA = 2i+1 (center in ce; dn = k 2i+2)
        {
            const float* rA = ROWP(2 * i + 1);
            const float* rD = ROWP(2 * i + 2);
            ACCUM(rA, *(const float4*)(rD + lc), *(const float4*)(rD + ROWF + lc));
        }
        // row kB = 2i+2 (center now in ce; dn = k 2i+3)
        {
            const float* rB = ROWP(2 * i + 2);
            const float* rD = ROWP(2 * i + 3);
            ACCUM(rB, *(const float4*)(rD + lc), *(const float4*)(rD + ROWF + lc));
        }
    }

    cp_wait0();   // retire dummy group before exit

    // ---- reduction ----
#pragma unroll
    for (int off = 16; off > 0; off >>= 1)
        s += __shfl_xor_sync(0xFFFFFFFFu, s, off);

    if (lane == 0) warp_part[wid] = s;
    __syncthreads();

    if (t == 0) {
        double bs = 0.0;
#pragma unroll
        for (int ww = 0; ww < 8; ww++) bs += (double)warp_part[ww];
        atomicAdd(&g_acc, bs);
        __threadfence();
        const unsigned prev = atomicAdd(&g_count, 1u);
        if (prev == NBLOCKS - 1) {
            const double total = atomicAdd(&g_acc, 0.0);
            out[0] = (float)(1.0 - total / (double)NPIX);
            g_acc = 0.0;          // reset for next graph replay
            g_count = 0u;
            __threadfence();
        }
    }
}

extern "C" void kernel_launch(void* const* d_in, const int* in_sizes, int n_in,
                              void* d_out, int out_size)
{
    const float* I0 = (const float*)d_in[0];
    const float* I1 = (const float*)d_in[1];
    float* out = (float*)d_out;

    cudaFuncSetAttribute(ngf_kernel, cudaFuncAttributeMaxDynamicSharedMemorySize, SMEM_BYTES);
    ngf_kernel<<<NBLOCKS, 256, SMEM_BYTES>>>(I0, I1, out);
}